// round 1
// baseline (speedup 1.0000x reference)
#include <cuda_runtime.h>

#define BB 8
#define LL 128
#define HH 768
#define NLAB 3

// Scratch accumulators (allocation-free rule: __device__ globals)
__device__ float g_sum[BB * HH];
__device__ float g_cnt[BB * HH];

__global__ void zero_k() {
    int i = blockIdx.x * blockDim.x + threadIdx.x;
    if (i < BB * HH) { g_sum[i] = 0.f; g_cnt[i] = 0.f; }
}

__global__ __launch_bounds__(256) void attn_k(
    const float* __restrict__ seq,    // [B,L,H]
    const float* __restrict__ Wk,     // [VOCAB,H]
    const float* __restrict__ Wv,     // [FEAT_VOCAB,H]
    const int*   __restrict__ valid,  // [B,L]
    const int*   __restrict__ kvidx,  // [B,L]
    const int*   __restrict__ feat,   // [B,L,L]
    const int*   __restrict__ posm,   // [B,L,L]
    const int*   __restrict__ asp)    // [B,L]
{
    const int b    = blockIdx.x / LL;
    const int q    = blockIdx.x % LL;
    const int tid  = threadIdx.x;
    const int lane = tid & 31;
    const int wid  = tid >> 5;

    __shared__ __align__(16) float hid[HH];
    __shared__ float uk[LL];
    __shared__ float cp_p[LL];
    __shared__ int   cp_i[LL];
    __shared__ int   fidx[LL];
    __shared__ int   wsum[4];
    __shared__ int   s_src;
    __shared__ int   s_nact;
    __shared__ float warp_red[8];
    __shared__ float s_dsum;

    if (tid == 0) { s_src = -1; s_nact = 0; }

    // ---- stable-partition scan: find source row = q-th valid position ----
    int v = 0;
    unsigned mask = 0;
    if (tid < LL) v = valid[b * LL + tid];
    if (wid < 4) {
        mask = __ballot_sync(0xFFFFFFFFu, v != 0);
        if (lane == 0) wsum[wid] = __popc(mask);
    }
    if (tid < LL) fidx[tid] = feat[(b * LL + q) * LL + tid];
    __syncthreads();
    if (wid < 4 && v) {
        int pref = __popc(mask & ((1u << lane) - 1u));   // exclusive prefix
        if (wid > 0) pref += wsum[0];
        if (wid > 1) pref += wsum[1];
        if (wid > 2) pref += wsum[2];
        if (pref == q) s_src = tid;    // this token is the q-th valid one
    }
    __syncthreads();

    const int   aspv = asp[b * LL + q];
    const int   src  = s_src;                 // >=0 iff q < count
    const bool  hz   = (src < 0) || (aspv == 0);
    const float aspf = (float)aspv;

    // ---- stage hidden[b,q,:] in smem ----
    for (int h = tid; h < HH; h += 256)
        hid[h] = hz ? 0.f : aspf * seq[(size_t)(b * LL + src) * HH + h];
    __syncthreads();

    // ---- u[k] = dot(hid, Wk[kvidx[b,k]]) / sqrt(H); 8 warps x 16 k ----
    const float invscale = 1.0f / 27.712812921102035f;  // 1/sqrt(768)
    for (int j = 0; j < 16; ++j) {
        int k = wid * 16 + j;
        int idx = kvidx[b * LL + k];
        float s = 0.f;
        if (!hz && idx != 0) {                 // padding_idx=0 => zero row
            const float4* row = (const float4*)(Wk + (size_t)idx * HH);
            const float4* hv  = (const float4*)hid;
            #pragma unroll
            for (int i = lane; i < HH / 4; i += 32) {
                float4 a = row[i]; float4 c = hv[i];
                s += a.x * c.x + a.y * c.y + a.z * c.z + a.w * c.w;
            }
            #pragma unroll
            for (int off = 16; off; off >>= 1)
                s += __shfl_xor_sync(0xFFFFFFFFu, s, off);
        }
        if (lane == 0) uk[k] = s * invscale;
    }
    __syncthreads();

    // ---- delta = exp(u) * pos; block-sum; p = delta / (sum + 1e-10) ----
    float dloc = 0.f;
    if (tid < LL) {
        int pm = posm[(b * LL + q) * LL + tid];
        if (pm != 0) dloc = expf(uk[tid]) * (float)pm;
    }
    float r = dloc;
    #pragma unroll
    for (int off = 16; off; off >>= 1) r += __shfl_xor_sync(0xFFFFFFFFu, r, off);
    if (lane == 0) warp_red[wid] = r;
    __syncthreads();
    if (tid == 0) {
        float t = 0.f;
        #pragma unroll
        for (int w = 0; w < 8; ++w) t += warp_red[w];
        s_dsum = t;
    }
    __syncthreads();
    const float inv = 1.f / (s_dsum + 1e-10f);

    // ---- compact active k (p != 0 && feature row != 0) ----
    if (tid < LL && dloc != 0.f) {
        int idx = fidx[tid];
        if (idx != 0) {
            int slot = atomicAdd(&s_nact, 1);
            cp_p[slot] = dloc * inv;
            cp_i[slot] = idx;
        }
    }
    __syncthreads();
    const int nact = s_nact;

    // ---- o[b,q,:] = sum_k p_k * Wv[idx_k,:]; 192 threads x float4 ----
    if (tid < 192) {
        float4 acc = make_float4(0.f, 0.f, 0.f, 0.f);
        const float4* WvV = (const float4*)Wv;
        #pragma unroll 4
        for (int m = 0; m < nact; ++m) {
            float  pk = cp_p[m];
            float4 vv = WvV[(size_t)cp_i[m] * (HH / 4) + tid];
            acc.x += pk * vv.x; acc.y += pk * vv.y;
            acc.z += pk * vv.z; acc.w += pk * vv.w;
        }
        int h0 = tid * 4;
        float* sp = g_sum + b * HH + h0;
        float* cp = g_cnt + b * HH + h0;
        atomicAdd(sp + 0, acc.x);
        atomicAdd(sp + 1, acc.y);
        atomicAdd(sp + 2, acc.z);
        atomicAdd(sp + 3, acc.w);
        atomicAdd(cp + 0, acc.x != 0.f ? 1.f : 0.f);
        atomicAdd(cp + 1, acc.y != 0.f ? 1.f : 0.f);
        atomicAdd(cp + 2, acc.z != 0.f ? 1.f : 0.f);
        atomicAdd(cp + 3, acc.w != 0.f ? 1.f : 0.f);
    }
}

__global__ __launch_bounds__(256) void head_k(
    const float* __restrict__ pooled,  // [B,H]
    const float* __restrict__ Wd,      // [3,2H]
    const float* __restrict__ bd,      // [3]
    float*       __restrict__ out)     // [B,3]
{
    const int b   = blockIdx.x;
    const int tid = threadIdx.x;
    __shared__ float c[2 * HH];
    __shared__ float warp_red[8];

    for (int i = tid; i < HH; i += 256) c[i] = pooled[b * HH + i];
    for (int i = tid; i < HH; i += 256)
        c[HH + i] = g_sum[b * HH + i] / g_cnt[b * HH + i];  // avg_o = sum/aspect_len
    __syncthreads();

    for (int n = 0; n < NLAB; ++n) {
        float s = 0.f;
        const float* w = Wd + n * 2 * HH;
        for (int i = tid; i < 2 * HH; i += 256) s += c[i] * w[i];
        #pragma unroll
        for (int off = 16; off; off >>= 1) s += __shfl_xor_sync(0xFFFFFFFFu, s, off);
        if ((tid & 31) == 0) warp_red[tid >> 5] = s;
        __syncthreads();
        if (tid == 0) {
            float t = 0.f;
            #pragma unroll
            for (int w2 = 0; w2 < 8; ++w2) t += warp_red[w2];
            out[b * NLAB + n] = t + bd[n];
        }
        __syncthreads();
    }
}

extern "C" void kernel_launch(void* const* d_in, const int* in_sizes, int n_in,
                              void* d_out, int out_size) {
    const float* seq    = (const float*)d_in[0];   // sequence_output [8,128,768]
    const float* pooled = (const float*)d_in[1];   // pooled_output  [8,768]
    const float* Wk     = (const float*)d_in[2];   // W_key  [30522,768]
    const float* Wv     = (const float*)d_in[3];   // W_val  [16384,768]
    const float* Wd     = (const float*)d_in[4];   // W_dense [3,1536]
    const float* bd     = (const float*)d_in[5];   // b_dense [3]
    const int*   valid  = (const int*)d_in[6];     // valid_ids [8,128]
    const int*   kvidx  = (const int*)d_in[7];     // text_kv_indices [8,128]
    const int*   feat   = (const int*)d_in[8];     // features [8,128,128]
    const int*   posm   = (const int*)d_in[9];     // pos_matrix [8,128,128]
    const int*   asp    = (const int*)d_in[10];    // aspect_indices [8,128]

    zero_k<<<(BB * HH + 255) / 256, 256>>>();
    attn_k<<<BB * LL, 256>>>(seq, Wk, Wv, valid, kvidx, feat, posm, asp);
    head_k<<<BB, 256>>>(pooled, Wd, bd, (float*)d_out);
}

// round 4
// speedup vs baseline: 1.0472x; 1.0472x over previous
#include <cuda_runtime.h>

#define BB 8
#define LL 128
#define HH 768
#define NLAB 3

// o scratch [B, L, H]  (allocation-free rule: __device__ global)
__device__ __align__(16) float g_o[BB * LL * HH];

__global__ __launch_bounds__(256) void attn_k(
    const float* __restrict__ seq,    // [B,L,H]
    const float* __restrict__ Wk,     // [VOCAB,H]
    const float* __restrict__ Wv,     // [FEAT_VOCAB,H]
    const int*   __restrict__ valid,  // [B,L]
    const int*   __restrict__ kvidx,  // [B,L]
    const int*   __restrict__ feat,   // [B,L,L]
    const int*   __restrict__ posm,   // [B,L,L]
    const int*   __restrict__ asp)    // [B,L]
{
    const int b    = blockIdx.x / LL;
    const int q    = blockIdx.x % LL;
    const int tid  = threadIdx.x;
    const int lane = tid & 31;
    const int wid  = tid >> 5;

    __shared__ __align__(16) float hid[HH];
    __shared__ float uk[LL];
    __shared__ float cp_p[LL];
    __shared__ int   cp_i[LL];
    __shared__ int   fidx[LL];
    __shared__ int   wsum[4];
    __shared__ int   s_src;
    __shared__ int   s_nact;
    __shared__ float warp_red[8];
    __shared__ float s_dsum;

    if (tid == 0) { s_src = -1; s_nact = 0; }

    // ---- stable-partition scan: source row = q-th valid position ----
    int v = 0;
    unsigned mask = 0;
    if (tid < LL) v = valid[b * LL + tid];
    if (wid < 4) {
        mask = __ballot_sync(0xFFFFFFFFu, v != 0);
        if (lane == 0) wsum[wid] = __popc(mask);
    }
    if (tid < LL) fidx[tid] = feat[(b * LL + q) * LL + tid];
    __syncthreads();
    if (wid < 4 && v) {
        int pref = __popc(mask & ((1u << lane) - 1u));
        if (wid > 0) pref += wsum[0];
        if (wid > 1) pref += wsum[1];
        if (wid > 2) pref += wsum[2];
        if (pref == q) s_src = tid;
    }
    __syncthreads();

    const int   aspv = asp[b * LL + q];
    const int   src  = s_src;
    const bool  hz   = (src < 0) || (aspv == 0);   // hidden row is all-zero
    const float aspf = (float)aspv;

    // ---- stage hidden[b,q,:] ----
    for (int h = tid; h < HH; h += 256)
        hid[h] = hz ? 0.f : aspf * seq[(size_t)(b * LL + src) * HH + h];
    __syncthreads();

    // ---- u[k] = dot(hid, Wk[kvidx[b,k]]) / sqrt(H); skip entirely if hz ----
    const float invscale = 1.0f / 27.712812921102035f;  // 1/sqrt(768)
    if (!hz) {
        #pragma unroll 1
        for (int j = 0; j < 16; ++j) {
            int k = wid * 16 + j;
            int idx = kvidx[b * LL + k];
            float s = 0.f;
            if (idx != 0) {               // padding_idx=0 -> zero row
                const float4* row = (const float4*)(Wk + (size_t)idx * HH);
                const float4* hv  = (const float4*)hid;
                #pragma unroll
                for (int i = lane; i < HH / 4; i += 32) {
                    float4 a = __ldg(row + i); float4 c = hv[i];
                    s += a.x * c.x + a.y * c.y + a.z * c.z + a.w * c.w;
                }
                #pragma unroll
                for (int off = 16; off; off >>= 1)
                    s += __shfl_xor_sync(0xFFFFFFFFu, s, off);
            }
            if (lane == 0) uk[k] = s * invscale;
        }
        __syncthreads();
    }

    // ---- delta = exp(u)*pos; block sum; compact active (p, idx) ----
    float dloc = 0.f;
    if (tid < LL) {
        int pm = posm[(b * LL + q) * LL + tid];
        if (pm != 0) dloc = hz ? 1.f : expf(uk[tid]);   // exp(0)=1 when hz
    }
    float r = dloc;
    #pragma unroll
    for (int off = 16; off; off >>= 1) r += __shfl_xor_sync(0xFFFFFFFFu, r, off);
    if (lane == 0) warp_red[wid] = r;
    __syncthreads();
    if (tid == 0) {
        float t = 0.f;
        #pragma unroll
        for (int w = 0; w < 8; ++w) t += warp_red[w];
        s_dsum = t;
    }
    __syncthreads();
    const float inv = 1.f / (s_dsum + 1e-10f);

    if (tid < LL && dloc != 0.f) {
        int idx = fidx[tid];
        if (idx != 0) {
            int slot = atomicAdd(&s_nact, 1);
            cp_p[slot] = dloc * inv;
            cp_i[slot] = idx;
        }
    }
    __syncthreads();
    const int nact = s_nact;

    // ---- o[b,q,:] = sum_m p_m * Wv[idx_m,:]; 192 threads x float4 ----
    if (tid < 192) {
        float4 acc = make_float4(0.f, 0.f, 0.f, 0.f);
        const float4* WvV = (const float4*)Wv;
        #pragma unroll 8
        for (int m = 0; m < nact; ++m) {
            float  pk = cp_p[m];
            float4 vv = __ldg(WvV + (size_t)cp_i[m] * (HH / 4) + tid);
            acc.x += pk * vv.x; acc.y += pk * vv.y;
            acc.z += pk * vv.z; acc.w += pk * vv.w;
        }
        ((float4*)(g_o + (size_t)(b * LL + q) * HH))[tid] = acc;
    }
}

// grid = B, block = 768: thread t owns h-column t
__global__ __launch_bounds__(768) void reduce_head_k(
    const float* __restrict__ pooled,  // [B,H]
    const float* __restrict__ Wd,      // [3,2H]
    const float* __restrict__ bd,      // [3]
    float*       __restrict__ out)     // [B,3]
{
    const int b   = blockIdx.x;
    const int t   = threadIdx.x;      // 0..767
    const int lane = t & 31;
    const int wid  = t >> 5;          // 0..23

    __shared__ float wred[24][NLAB];

    const float* ob = g_o + (size_t)b * LL * HH + t;
    float s = 0.f, c = 0.f;
    #pragma unroll 4
    for (int l = 0; l < LL; ++l) {
        float vv = ob[(size_t)l * HH];
        s += vv;
        c += (vv != 0.f) ? 1.f : 0.f;
    }
    const float avg = s / c;                       // avg_o = sum / aspect_len
    const float pv  = pooled[b * HH + t];

    float part[NLAB];
    #pragma unroll
    for (int n = 0; n < NLAB; ++n)
        part[n] = pv * Wd[n * 2 * HH + t] + avg * Wd[n * 2 * HH + HH + t];

    #pragma unroll
    for (int n = 0; n < NLAB; ++n) {
        float x = part[n];
        #pragma unroll
        for (int off = 16; off; off >>= 1) x += __shfl_xor_sync(0xFFFFFFFFu, x, off);
        if (lane == 0) wred[wid][n] = x;
    }
    __syncthreads();
    if (t < NLAB) {
        float tot = bd[t];
        #pragma unroll
        for (int w = 0; w < 24; ++w) tot += wred[w][t];
        out[b * NLAB + t] = tot;
    }
}

extern "C" void kernel_launch(void* const* d_in, const int* in_sizes, int n_in,
                              void* d_out, int out_size) {
    const float* seq    = (const float*)d_in[0];
    const float* pooled = (const float*)d_in[1];
    const float* Wk     = (const float*)d_in[2];
    const float* Wv     = (const float*)d_in[3];
    const float* Wd     = (const float*)d_in[4];
    const float* bd     = (const float*)d_in[5];
    const int*   valid  = (const int*)d_in[6];
    const int*   kvidx  = (const int*)d_in[7];
    const int*   feat   = (const int*)d_in[8];
    const int*   posm   = (const int*)d_in[9];
    const int*   asp    = (const int*)d_in[10];

    attn_k<<<BB * LL, 256>>>(seq, Wk, Wv, valid, kvidx, feat, posm, asp);
    reduce_head_k<<<BB, 768>>>(pooled, Wd, bd, (float*)d_out);
}

// round 5
// speedup vs baseline: 1.2202x; 1.1652x over previous
#include <cuda_runtime.h>

#define BB 8
#define LL 128
#define HH 768
#define NLAB 3

// o scratch [B, L, H]  (allocation-free rule: __device__ global)
__device__ __align__(16) float g_o[BB * LL * HH];

__global__ __launch_bounds__(256) void attn_k(
    const float* __restrict__ seq,    // [B,L,H]
    const float* __restrict__ Wk,     // [VOCAB,H]
    const float* __restrict__ Wv,     // [FEAT_VOCAB,H]
    const int*   __restrict__ valid,  // [B,L]
    const int*   __restrict__ kvidx,  // [B,L]
    const int*   __restrict__ feat,   // [B,L,L]
    const int*   __restrict__ posm,   // [B,L,L]
    const int*   __restrict__ asp)    // [B,L]
{
    const int b    = blockIdx.x / LL;
    const int q    = blockIdx.x % LL;
    const int tid  = threadIdx.x;
    const int lane = tid & 31;
    const int wid  = tid >> 5;

    __shared__ __align__(16) float hid[HH];
    __shared__ float uk[LL];
    __shared__ float cp_p[LL];
    __shared__ int   cp_i[LL];
    __shared__ int   fidx[LL];
    __shared__ int   wsum[4];
    __shared__ int   s_src;
    __shared__ int   s_nact;
    __shared__ float warp_red[8];
    __shared__ float s_dsum;

    if (tid == 0) { s_src = -1; s_nact = 0; }

    // ---- stable-partition scan: source row = q-th valid position ----
    int v = 0;
    unsigned mask = 0;
    if (tid < LL) v = valid[b * LL + tid];
    if (wid < 4) {
        mask = __ballot_sync(0xFFFFFFFFu, v != 0);
        if (lane == 0) wsum[wid] = __popc(mask);
    }
    if (tid < LL) fidx[tid] = feat[(b * LL + q) * LL + tid];
    __syncthreads();
    if (wid < 4 && v) {
        int pref = __popc(mask & ((1u << lane) - 1u));
        if (wid > 0) pref += wsum[0];
        if (wid > 1) pref += wsum[1];
        if (wid > 2) pref += wsum[2];
        if (pref == q) s_src = tid;
    }
    __syncthreads();

    const int   aspv = asp[b * LL + q];
    const int   src  = s_src;
    const bool  hz   = (src < 0) || (aspv == 0);   // hidden row is all-zero
    const float aspf = (float)aspv;

    // ---- stage hidden[b,q,:] ----
    for (int h = tid; h < HH; h += 256)
        hid[h] = hz ? 0.f : aspf * seq[(size_t)(b * LL + src) * HH + h];
    __syncthreads();

    // ---- u[k] = dot(hid, Wk[kvidx[b,k]]) / sqrt(H); skip entirely if hz ----
    const float invscale = 1.0f / 27.712812921102035f;  // 1/sqrt(768)
    if (!hz) {
        #pragma unroll 1
        for (int j = 0; j < 16; ++j) {
            int k = wid * 16 + j;
            int idx = kvidx[b * LL + k];
            float s = 0.f;
            if (idx != 0) {               // padding_idx=0 -> zero row
                const float4* row = (const float4*)(Wk + (size_t)idx * HH);
                const float4* hv  = (const float4*)hid;
                #pragma unroll
                for (int i = lane; i < HH / 4; i += 32) {
                    float4 a = __ldg(row + i); float4 c = hv[i];
                    s += a.x * c.x + a.y * c.y + a.z * c.z + a.w * c.w;
                }
                #pragma unroll
                for (int off = 16; off; off >>= 1)
                    s += __shfl_xor_sync(0xFFFFFFFFu, s, off);
            }
            if (lane == 0) uk[k] = s * invscale;
        }
        __syncthreads();
    }

    // ---- delta = exp(u)*pos; block sum; compact active (p, idx) ----
    float dloc = 0.f;
    if (tid < LL) {
        int pm = posm[(b * LL + q) * LL + tid];
        if (pm != 0) dloc = hz ? 1.f : expf(uk[tid]);   // exp(0)=1 when hz
    }
    float r = dloc;
    #pragma unroll
    for (int off = 16; off; off >>= 1) r += __shfl_xor_sync(0xFFFFFFFFu, r, off);
    if (lane == 0) warp_red[wid] = r;
    __syncthreads();
    if (tid == 0) {
        float t = 0.f;
        #pragma unroll
        for (int w = 0; w < 8; ++w) t += warp_red[w];
        s_dsum = t;
    }
    __syncthreads();
    const float inv = 1.f / (s_dsum + 1e-10f);

    if (tid < LL && dloc != 0.f) {
        int idx = fidx[tid];
        if (idx != 0) {
            int slot = atomicAdd(&s_nact, 1);
            cp_p[slot] = dloc * inv;
            cp_i[slot] = idx;
        }
    }
    __syncthreads();
    const int nact = s_nact;

    // ---- o[b,q,:] = sum_m p_m * Wv[idx_m,:]; 192 threads x float4 ----
    if (tid < 192) {
        float4 acc = make_float4(0.f, 0.f, 0.f, 0.f);
        const float4* WvV = (const float4*)Wv;
        #pragma unroll 8
        for (int m = 0; m < nact; ++m) {
            float  pk = cp_p[m];
            float4 vv = __ldg(WvV + (size_t)cp_i[m] * (HH / 4) + tid);
            acc.x += pk * vv.x; acc.y += pk * vv.y;
            acc.z += pk * vv.z; acc.w += pk * vv.w;
        }
        ((float4*)(g_o + (size_t)(b * LL + q) * HH))[tid] = acc;
    }
}

// grid = B, block = 768: thread t owns h-column t.
// Explicit 16-wide load batching -> MLP=16 (was the 23us bottleneck at MLP~4).
__global__ __launch_bounds__(768) void reduce_head_k(
    const float* __restrict__ pooled,  // [B,H]
    const float* __restrict__ Wd,      // [3,2H]
    const float* __restrict__ bd,      // [3]
    float*       __restrict__ out)     // [B,3]
{
    const int b    = blockIdx.x;
    const int t    = threadIdx.x;      // 0..767
    const int lane = t & 31;
    const int wid  = t >> 5;           // 0..23

    __shared__ float wred[24][NLAB];

    const float* ob = g_o + (size_t)b * LL * HH + t;
    float s = 0.f, c = 0.f;
    #pragma unroll 1
    for (int l0 = 0; l0 < LL; l0 += 16) {
        float vv[16];
        #pragma unroll
        for (int j = 0; j < 16; ++j)
            vv[j] = ob[(size_t)(l0 + j) * HH];      // 16 independent LDGs
        #pragma unroll
        for (int j = 0; j < 16; ++j) {
            s += vv[j];
            c += (vv[j] != 0.f) ? 1.f : 0.f;
        }
    }
    const float avg = s / c;                        // avg_o = sum / aspect_len
    const float pv  = pooled[b * HH + t];

    float part[NLAB];
    #pragma unroll
    for (int n = 0; n < NLAB; ++n)
        part[n] = pv * Wd[n * 2 * HH + t] + avg * Wd[n * 2 * HH + HH + t];

    #pragma unroll
    for (int n = 0; n < NLAB; ++n) {
        float x = part[n];
        #pragma unroll
        for (int off = 16; off; off >>= 1) x += __shfl_xor_sync(0xFFFFFFFFu, x, off);
        if (lane == 0) wred[wid][n] = x;
    }
    __syncthreads();
    if (t < NLAB) {
        float tot = bd[t];
        #pragma unroll
        for (int w = 0; w < 24; ++w) tot += wred[w][t];
        out[b * NLAB + t] = tot;
    }
}

extern "C" void kernel_launch(void* const* d_in, const int* in_sizes, int n_in,
                              void* d_out, int out_size) {
    const float* seq    = (const float*)d_in[0];
    const float* pooled = (const float*)d_in[1];
    const float* Wk     = (const float*)d_in[2];
    const float* Wv     = (const float*)d_in[3];
    const float* Wd     = (const float*)d_in[4];
    const float* bd     = (const float*)d_in[5];
    const int*   valid  = (const int*)d_in[6];
    const int*   kvidx  = (const int*)d_in[7];
    const int*   feat   = (const int*)d_in[8];
    const int*   posm   = (const int*)d_in[9];
    const int*   asp    = (const int*)d_in[10];

    attn_k<<<BB * LL, 256>>>(seq, Wk, Wv, valid, kvidx, feat, posm, asp);
    reduce_head_k<<<BB, 768>>>(pooled, Wd, bd, (float*)d_out);
}